// round 17
// baseline (speedup 1.0000x reference)
#include <cuda_runtime.h>
#include <cuda_fp16.h>
#include <cstdint>

#define Bb 128
#define Ss 128
#define ISZ 384
#define HSZ 768
#define GSZ 3072
#define HID (Bb*Ss*HSZ)
#define STATE (Bb*HSZ)
#define NREC 96
#define NPROD 24
#define NCTAR (NREC + NPROD)
#define RTHREADS 512

// ---------------- device scratch ----------------
__device__ __half g_Uf[GSZ*HSZ];              // Um^T permuted fp16 [n][k]
__device__ __half g_Wf[GSZ*ISZ];              // Wm^T permuted fp16 [n][k]
__device__ __half g_Xf[Bb*Ss*ISZ];            // x fp16 [(s*128+b)][k]
__device__ float g_xgr[4*(size_t)Bb*GSZ];     // xg RING: 4 slots x [b][n] (6 MB, L2-resident)
__device__ __half g_Hf[STATE];                // h fp16 [b][k]
__device__ float g_ct[STATE];                 // c fp32 [b][j]
__device__ float g_biasp[GSZ];
__device__ unsigned g_cnt;
__device__ volatile unsigned g_epoch;

// ---------------- helpers ----------------
__device__ __forceinline__ uint32_t smem_u32(const void* p) {
    uint32_t a;
    asm("{ .reg .u64 t; cvta.to.shared.u64 t, %1; cvt.u32.u64 %0, t; }" : "=r"(a) : "l"(p));
    return a;
}
__device__ __forceinline__ void ldsm4(uint32_t& r0, uint32_t& r1, uint32_t& r2, uint32_t& r3, uint32_t addr) {
    asm volatile("ldmatrix.sync.aligned.m8n8.x4.shared.b16 {%0,%1,%2,%3}, [%4];"
                 : "=r"(r0), "=r"(r1), "=r"(r2), "=r"(r3) : "r"(addr));
}
__device__ __forceinline__ void mma16816h(float* c, const uint32_t* a, uint32_t b0, uint32_t b1) {
    asm volatile("mma.sync.aligned.m16n8k16.row.col.f32.f16.f16.f32 "
                 "{%0,%1,%2,%3}, {%4,%5,%6,%7}, {%8,%9}, {%0,%1,%2,%3};"
                 : "+f"(c[0]), "+f"(c[1]), "+f"(c[2]), "+f"(c[3])
                 : "r"(a[0]), "r"(a[1]), "r"(a[2]), "r"(a[3]), "r"(b0), "r"(b1));
}
__device__ __forceinline__ float fsig(float x)  { return 1.0f / (1.0f + __expf(-x)); }
__device__ __forceinline__ float ftanh(float x) { return 2.0f / (1.0f + __expf(-2.0f * x)) - 1.0f; }

#define CP_ASYNC_CG(dst, src) asm volatile("cp.async.cg.shared.global [%0], [%1], 16;" :: "r"(dst), "l"(src))
#define CP_COMMIT()           asm volatile("cp.async.commit_group;" ::: "memory")
#define CP_WAIT0()            asm volatile("cp.async.wait_group 0;" ::: "memory")
#define CP_WAIT1()            asm volatile("cp.async.wait_group 1;" ::: "memory")
#define BAR_PAIR(id)          asm volatile("bar.sync %0, 64;" :: "r"(id) : "memory")

// full grid barrier; e = epoch value after release
__device__ __forceinline__ void gbar(unsigned e) {
    __syncthreads();
    if (threadIdx.x == 0) {
        __threadfence();
        if (atomicAdd(&g_cnt, 1u) == NCTAR - 1u) {
            g_cnt = 0;
            __threadfence();
            g_epoch = e;
        } else {
            while (g_epoch < e) { }
        }
        __threadfence();
    }
    __syncthreads();
}

// ================= recur SMEM layout =================
#define SB_BHI 0
#define SB_A   49152
#define SB_STG 98304
#define SB_CST 116736
#define SMEM2  120832
// producer overlays
#define XW_A 0u
#define XW_B 32768u

// ---------------- one-time conversions ----------------
__global__ void convAll(const float* __restrict__ x, const float* __restrict__ h0,
                        const float* __restrict__ c0, const float* __restrict__ W,
                        const float* __restrict__ U, const float* __restrict__ bias,
                        const float* __restrict__ G) {
    int idx = blockIdx.x * blockDim.x + threadIdx.x;
    if (idx == 0) { g_cnt = 0; g_epoch = 0; }
    if (idx < Bb * Ss * ISZ) {
        int f = idx % ISZ, r = idx / ISZ;
        int s = r >> 7, b = r & 127;
        g_Xf[idx] = __float2half_rn(x[((size_t)b * Ss + s) * ISZ + f]);
    }
    if (idx < GSZ * HSZ) {
        int n = idx / HSZ, k = idx % HSZ;
        int j = n >> 2, g = n & 3;
        g_Uf[idx] = __float2half_rn(U[(size_t)k * GSZ + g * HSZ + j] * G[(k >> 5) * 24 + (j >> 5)]);
    }
    if (idx < GSZ * ISZ) {
        int n = idx / ISZ, k = idx % ISZ;
        int j = n >> 2, g = n & 3;
        g_Wf[idx] = __float2half_rn(W[(size_t)k * GSZ + g * HSZ + j] * G[(k >> 4) * 24 + (j >> 5)]);
    }
    if (idx < STATE) {
        g_Hf[idx] = __float2half_rn(h0[idx]);
        g_ct[idx] = c0[idx];
        if (idx < GSZ) g_biasp[idx] = bias[(idx & 3) * HSZ + (idx >> 2)];
    }
}

__global__ void dummyK() {}

// ---------------- producer job: ring slot (s&3), cols [n0x, n0x+128) ----------------
// MMA math byte-identical to R15's proven xw_gemm (warps 0-7 compute; all 512 threads
// do the cooperative loads and final store; __syncthreads points are uniform).
__device__ void xw_job(char* smem, uint32_t sb, int s, int n0x) {
    const int tid = threadIdx.x, wid = tid >> 5, lane = tid & 31;
    const bool comp = (wid < 8);
    const int mb = (wid & 3) * 32, nb = ((wid & 7) >> 2) * 64;

    float c[2][8][4];
#pragma unroll
    for (int i = 0; i < 2; i++)
#pragma unroll
        for (int j = 0; j < 8; j++)
#pragma unroll
            for (int q = 0; q < 4; q++) c[i][j][q] = 0.0f;

    for (int ck = 0; ck < 3; ck++) {
        if (ck) __syncthreads();
        for (int i = tid; i < 4096; i += RTHREADS) {
            int ab = i >> 11;
            int r = i & 2047, row = r >> 4, kb = r & 15;
            const __half* src = ab
                ? g_Wf + (size_t)(n0x + row) * ISZ + ck * 128 + kb * 8
                : g_Xf + (size_t)(s * 128 + row) * ISZ + ck * 128 + kb * 8;
            uint32_t dst = (ab ? XW_B : XW_A) + (uint32_t)row * 256 + (uint32_t)((kb ^ (row & 7)) << 4);
            *reinterpret_cast<uint4*>(smem + dst) = *reinterpret_cast<const uint4*>(src);
        }
        __syncthreads();
        if (comp) {
#pragma unroll
            for (int k0 = 0; k0 < 8; k0++) {
                uint32_t a[2][4], b[4][4];
#pragma unroll
                for (int mi = 0; mi < 2; mi++) {
                    int rowA = mb + mi * 16 + (lane & 15);
                    int kbA = k0 * 2 + (lane >> 4);
                    ldsm4(a[mi][0], a[mi][1], a[mi][2], a[mi][3],
                          sb + XW_A + (uint32_t)rowA * 256 + (uint32_t)((kbA ^ (rowA & 7)) << 4));
                }
#pragma unroll
                for (int nj = 0; nj < 4; nj++) {
                    int rowB = nb + nj * 16 + ((lane >> 4) << 3) + (lane & 7);
                    int kbB = k0 * 2 + ((lane >> 3) & 1);
                    ldsm4(b[nj][0], b[nj][1], b[nj][2], b[nj][3],
                          sb + XW_B + (uint32_t)rowB * 256 + (uint32_t)((kbB ^ (rowB & 7)) << 4));
#pragma unroll
                    for (int mi = 0; mi < 2; mi++) {
                        mma16816h(c[mi][nj * 2],     a[mi], b[nj][0], b[nj][1]);
                        mma16816h(c[mi][nj * 2 + 1], a[mi], b[nj][2], b[nj][3]);
                    }
                }
            }
        }
    }
    if (comp) {
        const int col0 = n0x + nb + (lane & 3) * 2;
#pragma unroll
        for (int ni = 0; ni < 8; ni++) {
            float b0 = g_biasp[col0 + ni * 8];
            float b1 = g_biasp[col0 + ni * 8 + 1];
#pragma unroll
            for (int mi = 0; mi < 2; mi++) {
                c[mi][ni][0] += b0; c[mi][ni][1] += b1;
                c[mi][ni][2] += b0; c[mi][ni][3] += b1;
            }
        }
    }
    __syncthreads();
    {
        float* CS = reinterpret_cast<float*>(smem);
        if (comp) {
            const int r0 = mb + (lane >> 2);
            const int col0 = nb + (lane & 3) * 2;
#pragma unroll
            for (int mi = 0; mi < 2; mi++)
#pragma unroll
                for (int ni = 0; ni < 8; ni++) {
                    float* p0 = &CS[(r0 + mi * 16) * 132 + col0 + ni * 8];
                    p0[0] = c[mi][ni][0]; p0[1] = c[mi][ni][1];
                    float* p1 = &CS[(r0 + mi * 16 + 8) * 132 + col0 + ni * 8];
                    p1[0] = c[mi][ni][2]; p1[1] = c[mi][ni][3];
                }
        }
        __syncthreads();
        const int b2 = tid >> 2, q4 = tid & 3;
        const float4* src = reinterpret_cast<const float4*>(&CS[b2 * 132 + q4 * 32]);
        float4* dst = reinterpret_cast<float4*>(
            g_xgr + (size_t)(s & 3) * Bb * GSZ + (size_t)b2 * GSZ + n0x + q4 * 32);
#pragma unroll
        for (int q = 0; q < 8; q++) dst[q] = src[q];
    }
    __syncthreads();
}

// ---------------- recur A-chunk issue ----------------
__device__ __forceinline__ void issue_pairA(uint32_t sb, int mgrp, int pairLane, int kc, int buf) {
#pragma unroll
    for (int q = 0; q < 2; q++) {
        int idx = pairLane + 64 * q;
        int row16 = idx >> 3, kb = idx & 7;
        int b = mgrp * 16 + row16;
        const __half* src = g_Hf + (size_t)b * HSZ + kc * 64 + kb * 8;
        uint32_t dst = sb + SB_A + (uint32_t)buf * 16384u +
                       (uint32_t)b * 128u + (uint32_t)((kb ^ (b & 7)) << 4);
        CP_ASYNC_CG(dst, src);
    }
    CP_COMMIT();
}

// ---------------- fused persistent kernel ----------------
__global__ void __launch_bounds__(RTHREADS, 1) recurXW(float* __restrict__ out) {
    extern __shared__ char smem[];
    const uint32_t sb = smem_u32(smem);
    const int tid = threadIdx.x, wid = tid >> 5, lane = tid & 31;

    if (blockIdx.x >= NREC) {
        // ============ PRODUCER ============
        const int n0x = (blockIdx.x - NREC) * 128;
        xw_job(smem, sb, 0, n0x);
        xw_job(smem, sb, 1, n0x);
        gbar(1u);
        for (int s = 0; s < Ss; s++) {
            if (s + 2 < Ss) xw_job(smem, sb, s + 2, n0x);
            gbar((unsigned)(s + 2));
        }
        return;
    }

    // ============ RECURRENCE ============
    const int nt = blockIdx.x;
    const int n0 = nt * 32;
    const int j0 = nt * 8;

    for (int i = tid; i < 3072; i += RTHREADS) {
        int n = i / 96, kb = i % 96;
        const __half* src = g_Uf + (size_t)(n0 + n) * HSZ + kb * 8;
        uint32_t dst = SB_BHI + (uint32_t)n * 1536 + (uint32_t)((kb ^ (n & 7)) << 4);
        *reinterpret_cast<uint4*>(smem + dst) = *reinterpret_cast<const uint4*>(src);
    }
    float* cst = reinterpret_cast<float*>(smem + SB_CST);
    for (int i = tid; i < 1024; i += RTHREADS) {
        int b = i >> 3, jj = i & 7;
        cst[i] = g_ct[b * HSZ + j0 + jj];
    }
    float* stg = reinterpret_cast<float*>(smem + SB_STG);

    gbar(1u);    // xg[0], xg[1] published

    const int mgrp = wid & 7, ngrp = wid >> 3;
    const int mb = mgrp * 16, nbW = ngrp * 16;
    const int pairLane = ngrp * 32 + lane;
    const int barId = 1 + mgrp;
    const int bL = tid >> 2, qL = tid & 3;

    for (int s = 0; s < Ss; s++) {
        // read xg for THIS step (slot s&3; published >= 1 barrier ago; producer is
        // writing slot (s+2)&3 this round -> distance 2 mod 4, no alias)
        float4 xv[2];
        {
            const float* xgp = g_xgr + (size_t)(s & 3) * Bb * GSZ + (size_t)bL * GSZ + n0 + qL * 8;
            xv[0] = __ldcg(reinterpret_cast<const float4*>(xgp));
            xv[1] = __ldcg(reinterpret_cast<const float4*>(xgp + 4));
        }

        issue_pairA(sb, mgrp, pairLane, 0, 0);
        issue_pairA(sb, mgrp, pairLane, 1, 1);

        float c[2][4] = {};
        for (int kc = 0; kc < 12; kc++) {
            if (kc < 11) CP_WAIT1(); else CP_WAIT0();
            BAR_PAIR(barId);
            if (kc < 10) issue_pairA(sb, mgrp, pairLane, kc + 2, (kc + 2) % 3);

            const uint32_t abuf = sb + SB_A + (uint32_t)(kc % 3) * 16384u;
#pragma unroll
            for (int ks2 = 0; ks2 < 4; ks2++) {
                uint32_t ah[4], bh[4];
                int kbA = ks2 * 2 + (lane >> 4);
                int rowA = mb + (lane & 15);
                uint32_t offA = abuf + (uint32_t)rowA * 128 + (uint32_t)((kbA ^ (rowA & 7)) << 4);
                ldsm4(ah[0], ah[1], ah[2], ah[3], offA);
                int rowB = nbW + ((lane >> 4) << 3) + (lane & 7);
                int kbB = kc * 8 + ks2 * 2 + ((lane >> 3) & 1);
                uint32_t offB = (uint32_t)rowB * 1536 + (uint32_t)((kbB ^ (rowB & 7)) << 4);
                ldsm4(bh[0], bh[1], bh[2], bh[3], SB_BHI + sb + offB);
                mma16816h(c[0], ah, bh[0], bh[1]);
                mma16816h(c[1], ah, bh[2], bh[3]);
            }
        }

        {
            int r0 = mb + (lane >> 2);
            int col0 = nbW + (lane & 3) * 2;
#pragma unroll
            for (int nj = 0; nj < 2; nj++) {
                int col = col0 + nj * 8;
                stg[r0 * 36 + col]           = c[nj][0];
                stg[r0 * 36 + col + 1]       = c[nj][1];
                stg[(r0 + 8) * 36 + col]     = c[nj][2];
                stg[(r0 + 8) * 36 + col + 1] = c[nj][3];
            }
        }
        __syncthreads();

        float hq[2], cq[2];
        {
            const float* sp = stg + bL * 36 + qL * 8;
#pragma unroll
            for (int q = 0; q < 2; q++) {
                float vi = xv[q].x + sp[q * 4 + 0];
                float vf = xv[q].y + sp[q * 4 + 1];
                float vg = xv[q].z + sp[q * 4 + 2];
                float vo = xv[q].w + sp[q * 4 + 3];
                float ig = fsig(vi), fg = fsig(vf), gg = ftanh(vg), og = fsig(vo);
                int ci = bL * 8 + qL * 2 + q;
                float cc = fg * cst[ci] + ig * gg;
                cst[ci] = cc;
                hq[q] = og * ftanh(cc);
                cq[q] = cc;
            }
            __half2 hh;
            hh.x = __float2half_rn(hq[0]);
            hh.y = __float2half_rn(hq[1]);
            *reinterpret_cast<__half2*>(g_Hf + bL * HSZ + j0 + qL * 2) = hh;
        }

        // split grid barrier: arrive, shadow out-writes, wait
        __syncthreads();
        if (tid == 0) {
            __threadfence();
            if (atomicAdd(&g_cnt, 1u) == NCTAR - 1u) {
                g_cnt = 0;
                __threadfence();
                g_epoch = (unsigned)(s + 2);
            }
        }
        {
            int hoff = bL * HSZ + j0 + qL * 2;
            float2 hv = make_float2(hq[0], hq[1]);
            *reinterpret_cast<float2*>(out + ((size_t)bL * Ss + s) * HSZ + j0 + qL * 2) = hv;
            if (s == Ss - 1) {
                *reinterpret_cast<float2*>(out + HID + hoff) = hv;
                *reinterpret_cast<float2*>(out + HID + STATE + hoff) = make_float2(cq[0], cq[1]);
            }
        }
        if (tid == 0) {
            while (g_epoch < (unsigned)(s + 2)) { }
            __threadfence();
        }
        __syncthreads();
    }
}

extern "C" void kernel_launch(void* const* d_in, const int* in_sizes, int n_in,
                              void* d_out, int out_size) {
    const float* x    = (const float*)d_in[0];
    const float* h0   = (const float*)d_in[1];
    const float* c0   = (const float*)d_in[2];
    const float* W    = (const float*)d_in[3];
    const float* U    = (const float*)d_in[4];
    const float* bias = (const float*)d_in[5];
    const float* G    = (const float*)d_in[6];
    float* out = (float*)d_out;
    (void)in_sizes; (void)n_in; (void)out_size;

    cudaFuncSetAttribute(recurXW, cudaFuncAttributeMaxDynamicSharedMemorySize, SMEM2);

    convAll<<<(Bb * Ss * ISZ + 255) / 256, 256>>>(x, h0, c0, W, U, bias, G);
    dummyK<<<1, 1>>>();
    dummyK<<<1, 1>>>();
    recurXW<<<NCTAR, RTHREADS, SMEM2>>>(out);
}